// round 14
// baseline (speedup 1.0000x reference)
#include <cuda_runtime.h>
#include <cuda_fp16.h>
#include <cstdint>

#define BATCH 16
#define SEQ   256
#define DIM   512
#define G4    2048
#define LN_EPS 1e-5f

#define GROUPS 8                  // CTAs per batch
#define NCTA  (BATCH*GROUPS)     // 128
#define TPB   512
#define NWARP 16
#define KT    32                 // 16-wide k-tiles per row-block (512/16)
#define CKT   14                 // SMEM-cached k-tiles per layer per warp
#define PF    6                  // register-prefetched streamed tiles
#define WARP_CACHE_U4 (2*CKT*32)               // 896 uint4/warp
#define SMEM_W_BYTES (NWARP*WARP_CACHE_U4*16)  // 229376
#define OFF_H2  SMEM_W_BYTES                   // fp16 h buffer (1 KB)
#define OFF_RED (OFF_H2 + 1024)
#define OFF_C   (OFF_RED + NWARP*8)
#define SMEM_TOTAL (OFF_C + 16)               // ~230.5 KB, 1 CTA/SM

#define NFRAG ((size_t)BATCH*128*KT*32)        // uint4 fragment chunks (32 MB each)
#define NXF   ((size_t)BATCH*32*KT*32)         // x B-fragments (uint2): 4 MB

// ---------------- static device scratch ----------------
__device__ uint4   d_w0f[NFRAG];              // whh0, A-fragment-major fp16
__device__ uint4   d_w1f[NFRAG];              // wih1+whh1, A-fragment-major fp16
__device__ uint4   d_wxf[NFRAG];              // wih0, A-fragment-major fp16
__device__ uint2   d_xf [NXF];                // x, B-fragment-major fp16
__device__ float   d_pre0[(size_t)BATCH*SEQ*G4];
__device__ float   d_bias1[BATCH*G4];
__device__ float   d_gates[2*BATCH*G4];       // double-buffered by layer
__device__ float2  d_gstat[2*NCTA];
__device__ unsigned d_bar[BATCH*32];

// ---------------- helpers ----------------
__device__ __forceinline__ unsigned f2h2(float a, float b) {
    __half2 h = __floats2half2_rn(a, b);
    return *reinterpret_cast<unsigned*>(&h);
}
__device__ __forceinline__ float sigmoidf_(float x) {
    return __fdividef(1.f, 1.f + __expf(-x));
}
__device__ __forceinline__ float tanhf_(float x) {
    x = fminf(fmaxf(x, -12.f), 12.f);
    float t = __expf(2.f * x);
    return __fdividef(t - 1.f, t + 1.f);
}

#define MMA16816(d, v, hb)                                                        \
    asm volatile("mma.sync.aligned.m16n8k16.row.col.f32.f16.f16.f32 "             \
                 "{%0,%1,%2,%3},{%4,%5,%6,%7},{%8,%9},{%0,%1,%2,%3};"             \
                 : "+f"(d[0]), "+f"(d[1]), "+f"(d[2]), "+f"(d[3])                 \
                 : "r"(v.x), "r"(v.z), "r"(v.y), "r"(v.w), "r"(hb.x), "r"(hb.y))

// ---------------- prep: build A/B-fragment fp16 tensors ----------------
__global__ void prep_kernel(const float* __restrict__ x,
                            const float* __restrict__ wih0,
                            const float* __restrict__ whh0,
                            const float* __restrict__ wih1,
                            const float* __restrict__ whh1,
                            const float* __restrict__ bih1,
                            const float* __restrict__ bhh1)
{
    size_t idx0 = (size_t)blockIdx.x * blockDim.x + threadIdx.x;
    size_t stride = (size_t)gridDim.x * blockDim.x;
    for (size_t i = idx0; i < NFRAG; i += stride) {
        unsigned lane = (unsigned)i & 31u;
        unsigned kt   = ((unsigned)(i >> 5)) & 31u;
        unsigned blk  = ((unsigned)(i >> 10)) & 127u;
        unsigned b    = (unsigned)(i >> 17);
        unsigned gid  = lane >> 2, tig = lane & 3;
        size_t s0 = ((size_t)b * G4 + blk * 16 + gid) * DIM + kt * 16 + tig * 4;
        size_t s1 = s0 + 8 * DIM;
        {
            float4 A0 = *(const float4*)(whh0 + s0);
            float4 A1 = *(const float4*)(whh0 + s1);
            uint4 o;
            o.x = f2h2(A0.x, A0.y); o.y = f2h2(A0.z, A0.w);
            o.z = f2h2(A1.x, A1.y); o.w = f2h2(A1.z, A1.w);
            d_w0f[i] = o;
        }
        {
            float4 A0 = *(const float4*)(wih0 + s0);
            float4 A1 = *(const float4*)(wih0 + s1);
            uint4 o;
            o.x = f2h2(A0.x, A0.y); o.y = f2h2(A0.z, A0.w);
            o.z = f2h2(A1.x, A1.y); o.w = f2h2(A1.z, A1.w);
            d_wxf[i] = o;
        }
        {
            float4 U0 = *(const float4*)(wih1 + s0);
            float4 V0 = *(const float4*)(whh1 + s0);
            float4 U1 = *(const float4*)(wih1 + s1);
            float4 V1 = *(const float4*)(whh1 + s1);
            uint4 o;
            o.x = f2h2(U0.x + V0.x, U0.y + V0.y); o.y = f2h2(U0.z + V0.z, U0.w + V0.w);
            o.z = f2h2(U1.x + V1.x, U1.y + V1.y); o.w = f2h2(U1.z + V1.z, U1.w + V1.w);
            d_w1f[i] = o;
        }
    }
    // x B-fragments: d_xf[((b*32+tg)*KT+kt)*32+lane] = x[b][tg*8+gid][kt*16+tig*4 ..+3]
    for (size_t i = idx0; i < NXF; i += stride) {
        unsigned lane = (unsigned)i & 31u;
        unsigned kt   = ((unsigned)(i >> 5)) & 31u;
        unsigned tg   = ((unsigned)(i >> 10)) & 31u;
        unsigned b    = (unsigned)(i >> 15);
        unsigned gid  = lane >> 2, tig = lane & 3;
        float4 xv = *(const float4*)(x + ((size_t)(b * SEQ + tg * 8 + gid) * DIM
                                          + kt * 16 + tig * 4));
        d_xf[i] = make_uint2(f2h2(xv.x, xv.y), f2h2(xv.z, xv.w));
    }
    if (idx0 < BATCH * G4) d_bias1[idx0] = bih1[idx0] + bhh1[idx0];
    if (idx0 < BATCH * 32) d_bar[idx0] = 0u;
}

// ---- HMMA GEMM: d_pre0[b][t][j] = wih0[b]@x[b,t] + bih0 + bhh0 ----
__global__ void __launch_bounds__(256) gemm_pre0_h(const float* __restrict__ bih0,
                                                   const float* __restrict__ bhh0)
{
    extern __shared__ __align__(16) unsigned char gsm[];
    uint4* s_a = (uint4*)gsm;                      // 4 * KT * 32 uint4 = 64 KB

    const int b  = blockIdx.y;
    const int rg = blockIdx.x;                     // 0..31 -> rowblocks rg*4..rg*4+3
    const int tid = threadIdx.x;
    const int wid = tid >> 5;
    const int lane = tid & 31;
    const int gid = lane >> 2;
    const int tig = lane & 3;

    const uint4* Asrc = d_wxf + ((size_t)b * 128 + rg * 4) * (KT * 32);
    for (int i = tid; i < 4 * KT * 32; i += 256) s_a[i] = Asrc[i];
    __syncthreads();

    const int rb = wid >> 1;
    const int row0g = (rg * 4 + rb) * 16;
    const uint4* As = s_a + rb * (KT * 32);
    const float bias0 = __ldg(bih0 + b * G4 + row0g + gid)
                      + __ldg(bhh0 + b * G4 + row0g + gid);
    const float bias1 = __ldg(bih0 + b * G4 + row0g + gid + 8)
                      + __ldg(bhh0 + b * G4 + row0g + gid + 8);

    const int tg0 = (wid & 1) * 16;
    for (int tg = tg0; tg < tg0 + 16; tg++) {
        const uint2* xf = d_xf + ((size_t)(b * 32 + tg) * KT) * 32;
        float d0[4] = {0.f, 0.f, 0.f, 0.f};
        float d1[4] = {0.f, 0.f, 0.f, 0.f};
#pragma unroll
        for (int kt = 0; kt < KT; kt++) {
            uint4 v  = As[kt * 32 + lane];
            uint2 hb = __ldg(&xf[kt * 32 + lane]);
            if (kt & 1) { MMA16816(d1, v, hb); }
            else        { MMA16816(d0, v, hb); }
        }
        const int t = tg * 8;
        float* base = d_pre0 + ((size_t)b * SEQ + t) * G4;
        base[(2 * tig)     * G4 + row0g + gid]     = d0[0] + d1[0] + bias0;
        base[(2 * tig + 1) * G4 + row0g + gid]     = d0[1] + d1[1] + bias0;
        base[(2 * tig)     * G4 + row0g + gid + 8] = d0[2] + d1[2] + bias1;
        base[(2 * tig + 1) * G4 + row0g + gid + 8] = d0[3] + d1[3] + bias1;
    }
}

// ---------------- persistent LSTM kernel ----------------
__device__ __forceinline__ void group_barrier(unsigned* bar, unsigned* epoch, int tid) {
    __syncthreads();
    *epoch += GROUPS;
    unsigned target = *epoch;
    if (tid == 0) {
        asm volatile("red.release.gpu.global.add.u32 [%0],%1;"
                     :: "l"(bar), "r"(1u) : "memory");
        unsigned v;
        do {
            asm volatile("ld.acquire.gpu.global.u32 %0,[%1];"
                         : "=r"(v) : "l"(bar) : "memory");
        } while (v < target);
    }
    __syncthreads();
}

__global__ void __launch_bounds__(TPB, 1)
lstm_kernel(const float* __restrict__ lnw, const float* __restrict__ lnb,
            float* __restrict__ out)
{
    extern __shared__ __align__(16) unsigned char smem[];
    uint4*  s_w   = (uint4*)smem;
    __half* s_h2  = (__half*)(smem + OFF_H2);
    float2* s_red = (float2*)(smem + OFF_RED);

    const int cta = blockIdx.x;
    const int b   = cta >> 3;
    const int k   = cta & 7;
    const int tid = threadIdx.x;
    const int wid = tid >> 5;
    const int lane = tid & 31;
    const int gid = lane >> 2;
    const int tig = lane & 3;

    unsigned* bar = &d_bar[b * 32];
    unsigned epoch = 0;
    const int blk  = k * 16 + wid;        // global 16-row block id within batch
    const int row0 = blk * 16;

    const uint4* Wg0 = d_w0f + ((size_t)b * 128 + blk) * (KT * 32);
    const uint4* Wg1 = d_w1f + ((size_t)b * 128 + blk) * (KT * 32);

    // ---- fill SMEM fragment cache: per warp, tiles 0..CKT-1 of each layer ----
    for (int i = tid; i < NWARP * WARP_CACHE_U4; i += TPB) {
        int w  = i / WARP_CACHE_U4;
        int r  = i % WARP_CACHE_U4;
        int l  = r / (CKT * 32);
        int rr = r % (CKT * 32);           // kt*32 + lane
        const uint4* src = (l ? d_w1f : d_w0f)
                         + ((size_t)b * 128 + k * 16 + w) * (KT * 32) + rr;
        s_w[i] = *src;
    }

    const float gw0 = __ldg(lnw + tid),       gb0 = __ldg(lnb + tid);
    const float gw1 = __ldg(lnw + DIM + tid), gb1 = __ldg(lnb + DIM + tid);

    float creg = 0.f;
    ((unsigned short*)s_h2)[tid] = 0;      // h = 0 (fp16)

    // initial prefetch for (t=0, l=0)
    uint4 pf[PF];
#pragma unroll
    for (int j = 0; j < PF; j++) pf[j] = __ldcg(&Wg0[(CKT + j) * 32 + lane]);

    __syncthreads();

    for (int t = 0; t < SEQ; t++) {
#pragma unroll
        for (int l = 0; l < 2; l++) {
            const float* add = (l == 0) ? (d_pre0 + ((size_t)b * SEQ + t) * G4)
                                        : (d_bias1 + (size_t)b * G4);
            float* gates = d_gates + (size_t)l * BATCH * G4 + (size_t)b * G4;
            const uint4* Wg = l ? Wg1 : Wg0;
            const uint4* Ws = s_w + wid * WARP_CACHE_U4 + l * (CKT * 32);
            const char* hbp = (const char*)s_h2 + tig * 8;

            float da[4] = {0.f, 0.f, 0.f, 0.f};
            float db[4] = {0.f, 0.f, 0.f, 0.f};
#pragma unroll
            for (int kt = 0; kt < KT; kt++) {
                uint4 v = (kt < CKT) ? Ws[kt * 32 + lane]
                        : (kt < CKT + PF) ? pf[kt - CKT]
                                          : __ldcg(&Wg[kt * 32 + lane]);
                uint2 hb = *(const uint2*)(hbp + kt * 32);
                if (kt & 1) { MMA16816(db, v, hb); }
                else        { MMA16816(da, v, hb); }
            }
            // every lane's D col is the gate (h replicated over columns)
            float g0 = da[0] + db[0] + __ldg(add + row0 + gid);
            float g1 = da[2] + db[2] + __ldg(add + row0 + 8 + gid);
            if (tig == 0) {
                gates[row0 + gid]     = g0;
                gates[row0 + 8 + gid] = g1;
            }

            // ---- prefetch next layer's streamed tiles NOW: latency hides behind
            //      reduction + barrier spin + stats load (weights are static) ----
#pragma unroll
            for (int j = 0; j < PF; j++)
                pf[j] = __ldcg(&((l ? Wg0 : Wg1)[(CKT + j) * 32 + lane]));

            float s1 = g0 + g1;
            float s2 = fmaf(g0, g0, g1 * g1);
#pragma unroll
            for (int o = 16; o >= 4; o >>= 1) {      // sums lanes 0,4,...,28
                s1 += __shfl_down_sync(0xffffffffu, s1, o);
                s2 += __shfl_down_sync(0xffffffffu, s2, o);
            }
            if (lane == 0) s_red[wid] = make_float2(s1, s2);
            __syncthreads();
            if (tid == 0) {
                float a = 0.f, c = 0.f;
#pragma unroll
                for (int i = 0; i < NWARP; i++) { a += s_red[i].x; c += s_red[i].y; }
                d_gstat[l * NCTA + cta] = make_float2(a, c);
            }
            group_barrier(bar, &epoch, tid);

            // ---- pointwise (redundant per CTA) ----
            {
                const int d = tid;
                const float gw = (l == 0) ? gw0 : gw1;
                const float gb = (l == 0) ? gb0 : gb1;
                const float4* st4 = (const float4*)(&d_gstat[l * NCTA + b * 8]);
                float m_[4], r_[4];
#pragma unroll
                for (int q = 0; q < 4; q++) {
                    float4 sv = __ldcg(st4 + q);
                    float s  = sv.x + sv.z;
                    float ss = sv.y + sv.w;
                    float m  = s * (1.f / 512.f);
                    float v  = fmaf(-m, m, ss * (1.f / 512.f));
                    m_[q] = m;
                    r_[q] = rsqrtf(v + LN_EPS);
                }
                float xi = __ldcg(gates + d);
                float xf = __ldcg(gates + 512 + d);
                float xg = __ldcg(gates + 1024 + d);
                float xo = __ldcg(gates + 1536 + d);
                float iv = sigmoidf_(fmaf((xi - m_[0]) * r_[0], gw, gb));
                float fv = sigmoidf_(fmaf((xf - m_[1]) * r_[1], gw, gb));
                float gv = tanhf_(   fmaf((xg - m_[2]) * r_[2], gw, gb));
                float ov = sigmoidf_(fmaf((xo - m_[3]) * r_[3], gw, gb));
                float cn = fmaf(fv, creg, iv * gv);
                creg = cn;

                float a = cn, c2 = cn * cn;
#pragma unroll
                for (int o = 16; o > 0; o >>= 1) {
                    a  += __shfl_down_sync(0xffffffffu, a, o);
                    c2 += __shfl_down_sync(0xffffffffu, c2, o);
                }
                if (lane == 0) s_red[wid] = make_float2(a, c2);
                __syncthreads();
                // all threads redundantly finalize c-LN stats (no tid0 serial chain)
                float sa = 0.f, sb = 0.f;
#pragma unroll
                for (int i = 0; i < NWARP; i++) {
                    float2 v = s_red[i];
                    sa += v.x; sb += v.y;
                }
                float cm = sa * (1.f / 512.f);
                float cv = fmaf(-cm, cm, sb * (1.f / 512.f));
                float cr = rsqrtf(cv + LN_EPS);

                float hv = ov * tanhf_(fmaf((cn - cm) * cr, gw, gb));
                s_h2[d] = __float2half_rn(hv);
                if (l == 1 && k == 0)
                    out[((size_t)b * SEQ + t) * DIM + d] = hv;
                __syncthreads();   // s_h2 + s_red reads done before next layer
            }
        }
    }
}

extern "C" void kernel_launch(void* const* d_in, const int* in_sizes, int n_in,
                              void* d_out, int out_size) {
    const float* x    = (const float*)d_in[0];
    const float* wih0 = (const float*)d_in[1];
    const float* whh0 = (const float*)d_in[2];
    const float* bih0 = (const float*)d_in[3];
    const float* bhh0 = (const float*)d_in[4];
    const float* wih1 = (const float*)d_in[5];
    const float* whh1 = (const float*)d_in[6];
    const float* bih1 = (const float*)d_in[7];
    const float* bhh1 = (const float*)d_in[8];
    const float* ln_w = (const float*)d_in[9];
    const float* ln_b = (const float*)d_in[10];
    float* out = (float*)d_out;

    cudaFuncSetAttribute(lstm_kernel, cudaFuncAttributeMaxDynamicSharedMemorySize,
                         SMEM_TOTAL);
    cudaFuncSetAttribute(gemm_pre0_h, cudaFuncAttributeMaxDynamicSharedMemorySize,
                         4 * KT * 32 * 16);

    prep_kernel<<<1024, 256>>>(x, wih0, whh0, wih1, whh1, bih1, bhh1);
    gemm_pre0_h<<<dim3(32, 16), 256, 4 * KT * 32 * 16>>>(bih0, bhh0);
    lstm_kernel<<<NCTA, TPB, SMEM_TOTAL>>>(ln_w, ln_b, out);
}

// round 15
// speedup vs baseline: 1.0294x; 1.0294x over previous
#include <cuda_runtime.h>
#include <cuda_fp16.h>
#include <cstdint>

#define BATCH 16
#define SEQ   256
#define DIM   512
#define G4    2048
#define LN_EPS 1e-5f

#define GROUPS 8                  // CTAs per batch
#define NCTA  (BATCH*GROUPS)     // 128
#define TPB   512
#define NWARP 16
#define KT    32                 // 16-wide k-tiles per row-block (512/16)
#define CKT   14                 // SMEM-cached k-tiles per layer per warp
#define PF    6                  // register-prefetched streamed tiles
#define WARP_CACHE_U4 (2*CKT*32)               // 896 uint4/warp
#define SMEM_W_BYTES (NWARP*WARP_CACHE_U4*16)  // 229376
#define OFF_H2  SMEM_W_BYTES                   // fp16 h buffer (1 KB)
#define OFF_RED (OFF_H2 + 1024)
#define OFF_C   (OFF_RED + NWARP*8)
#define SMEM_TOTAL (OFF_C + 16)               // ~230.5 KB, 1 CTA/SM

#define NFRAG ((size_t)BATCH*128*KT*32)        // uint4 fragment chunks (32 MB each)
#define NXF   ((size_t)BATCH*32*KT*32)         // x B-fragments (uint2): 4 MB

// ---------------- static device scratch ----------------
__device__ uint4   d_w0f[NFRAG];              // whh0, A-fragment-major fp16
__device__ uint4   d_w1f[NFRAG];              // wih1+whh1, A-fragment-major fp16
__device__ uint4   d_wxf[NFRAG];              // wih0, A-fragment-major fp16
__device__ uint2   d_xf [NXF];                // x, B-fragment-major fp16
__device__ float   d_pre0[(size_t)BATCH*SEQ*G4];
__device__ float   d_bias1[BATCH*G4];
__device__ float   d_gates[2*BATCH*G4];       // double-buffered by layer
__device__ float2  d_gstat[2*NCTA];
__device__ unsigned d_bar[BATCH*32];

// ---------------- helpers ----------------
__device__ __forceinline__ unsigned f2h2(float a, float b) {
    __half2 h = __floats2half2_rn(a, b);
    return *reinterpret_cast<unsigned*>(&h);
}
__device__ __forceinline__ float sigmoidf_(float x) {
    return __fdividef(1.f, 1.f + __expf(-x));
}
__device__ __forceinline__ float tanhf_(float x) {
    x = fminf(fmaxf(x, -12.f), 12.f);
    float t = __expf(2.f * x);
    return __fdividef(t - 1.f, t + 1.f);
}

#define MMA16816(d, v, hb)                                                        \
    asm volatile("mma.sync.aligned.m16n8k16.row.col.f32.f16.f16.f32 "             \
                 "{%0,%1,%2,%3},{%4,%5,%6,%7},{%8,%9},{%0,%1,%2,%3};"             \
                 : "+f"(d[0]), "+f"(d[1]), "+f"(d[2]), "+f"(d[3])                 \
                 : "r"(v.x), "r"(v.z), "r"(v.y), "r"(v.w), "r"(hb.x), "r"(hb.y))

// ---------------- prep: build A/B-fragment fp16 tensors ----------------
__global__ void prep_kernel(const float* __restrict__ x,
                            const float* __restrict__ wih0,
                            const float* __restrict__ whh0,
                            const float* __restrict__ wih1,
                            const float* __restrict__ whh1,
                            const float* __restrict__ bih1,
                            const float* __restrict__ bhh1)
{
    size_t idx0 = (size_t)blockIdx.x * blockDim.x + threadIdx.x;
    size_t stride = (size_t)gridDim.x * blockDim.x;
    for (size_t i = idx0; i < NFRAG; i += stride) {
        unsigned lane = (unsigned)i & 31u;
        unsigned kt   = ((unsigned)(i >> 5)) & 31u;
        unsigned blk  = ((unsigned)(i >> 10)) & 127u;
        unsigned b    = (unsigned)(i >> 17);
        unsigned gid  = lane >> 2, tig = lane & 3;
        size_t s0 = ((size_t)b * G4 + blk * 16 + gid) * DIM + kt * 16 + tig * 4;
        size_t s1 = s0 + 8 * DIM;
        {
            float4 A0 = *(const float4*)(whh0 + s0);
            float4 A1 = *(const float4*)(whh0 + s1);
            uint4 o;
            o.x = f2h2(A0.x, A0.y); o.y = f2h2(A0.z, A0.w);
            o.z = f2h2(A1.x, A1.y); o.w = f2h2(A1.z, A1.w);
            d_w0f[i] = o;
        }
        {
            float4 A0 = *(const float4*)(wih0 + s0);
            float4 A1 = *(const float4*)(wih0 + s1);
            uint4 o;
            o.x = f2h2(A0.x, A0.y); o.y = f2h2(A0.z, A0.w);
            o.z = f2h2(A1.x, A1.y); o.w = f2h2(A1.z, A1.w);
            d_wxf[i] = o;
        }
        {
            float4 U0 = *(const float4*)(wih1 + s0);
            float4 V0 = *(const float4*)(whh1 + s0);
            float4 U1 = *(const float4*)(wih1 + s1);
            float4 V1 = *(const float4*)(whh1 + s1);
            uint4 o;
            o.x = f2h2(U0.x + V0.x, U0.y + V0.y); o.y = f2h2(U0.z + V0.z, U0.w + V0.w);
            o.z = f2h2(U1.x + V1.x, U1.y + V1.y); o.w = f2h2(U1.z + V1.z, U1.w + V1.w);
            d_w1f[i] = o;
        }
    }
    // x B-fragments: d_xf[((b*32+tg)*KT+kt)*32+lane] = x[b][tg*8+gid][kt*16+tig*4 ..+3]
    for (size_t i = idx0; i < NXF; i += stride) {
        unsigned lane = (unsigned)i & 31u;
        unsigned kt   = ((unsigned)(i >> 5)) & 31u;
        unsigned tg   = ((unsigned)(i >> 10)) & 31u;
        unsigned b    = (unsigned)(i >> 15);
        unsigned gid  = lane >> 2, tig = lane & 3;
        float4 xv = *(const float4*)(x + ((size_t)(b * SEQ + tg * 8 + gid) * DIM
                                          + kt * 16 + tig * 4));
        d_xf[i] = make_uint2(f2h2(xv.x, xv.y), f2h2(xv.z, xv.w));
    }
    if (idx0 < BATCH * G4) d_bias1[idx0] = bih1[idx0] + bhh1[idx0];
    if (idx0 < BATCH * 32) d_bar[idx0] = 0u;
}

// ---- HMMA GEMM: d_pre0[b][t][j] = wih0[b]@x[b,t] + bih0 + bhh0 ----
__global__ void __launch_bounds__(256) gemm_pre0_h(const float* __restrict__ bih0,
                                                   const float* __restrict__ bhh0)
{
    extern __shared__ __align__(16) unsigned char gsm[];
    uint4* s_a = (uint4*)gsm;                      // 4 * KT * 32 uint4 = 64 KB

    const int b  = blockIdx.y;
    const int rg = blockIdx.x;                     // 0..31 -> rowblocks rg*4..rg*4+3
    const int tid = threadIdx.x;
    const int wid = tid >> 5;
    const int lane = tid & 31;
    const int gid = lane >> 2;
    const int tig = lane & 3;

    const uint4* Asrc = d_wxf + ((size_t)b * 128 + rg * 4) * (KT * 32);
    for (int i = tid; i < 4 * KT * 32; i += 256) s_a[i] = Asrc[i];
    __syncthreads();

    const int rb = wid >> 1;
    const int row0g = (rg * 4 + rb) * 16;
    const uint4* As = s_a + rb * (KT * 32);
    const float bias0 = __ldg(bih0 + b * G4 + row0g + gid)
                      + __ldg(bhh0 + b * G4 + row0g + gid);
    const float bias1 = __ldg(bih0 + b * G4 + row0g + gid + 8)
                      + __ldg(bhh0 + b * G4 + row0g + gid + 8);

    const int tg0 = (wid & 1) * 16;
    for (int tg = tg0; tg < tg0 + 16; tg++) {
        const uint2* xf = d_xf + ((size_t)(b * 32 + tg) * KT) * 32;
        float d0[4] = {0.f, 0.f, 0.f, 0.f};
        float d1[4] = {0.f, 0.f, 0.f, 0.f};
#pragma unroll
        for (int kt = 0; kt < KT; kt++) {
            uint4 v  = As[kt * 32 + lane];
            uint2 hb = __ldg(&xf[kt * 32 + lane]);
            if (kt & 1) { MMA16816(d1, v, hb); }
            else        { MMA16816(d0, v, hb); }
        }
        const int t = tg * 8;
        float* base = d_pre0 + ((size_t)b * SEQ + t) * G4;
        base[(2 * tig)     * G4 + row0g + gid]     = d0[0] + d1[0] + bias0;
        base[(2 * tig + 1) * G4 + row0g + gid]     = d0[1] + d1[1] + bias0;
        base[(2 * tig)     * G4 + row0g + gid + 8] = d0[2] + d1[2] + bias1;
        base[(2 * tig + 1) * G4 + row0g + gid + 8] = d0[3] + d1[3] + bias1;
    }
}

// ---------------- persistent LSTM kernel ----------------
// Callers guarantee a __syncthreads already separates all threads' prior
// global stores from this call (sync -> elect -> release pattern), so the
// leading barrier is elided; only the post-spin sync remains.
__device__ __forceinline__ void group_barrier(unsigned* bar, unsigned* epoch, int tid) {
    *epoch += GROUPS;
    unsigned target = *epoch;
    if (tid == 0) {
        asm volatile("red.release.gpu.global.add.u32 [%0],%1;"
                     :: "l"(bar), "r"(1u) : "memory");
        unsigned v;
        do {
            asm volatile("ld.acquire.gpu.global.u32 %0,[%1];"
                         : "=r"(v) : "l"(bar) : "memory");
        } while (v < target);
    }
    __syncthreads();
}

__global__ void __launch_bounds__(TPB, 1)
lstm_kernel(const float* __restrict__ lnw, const float* __restrict__ lnb,
            float* __restrict__ out)
{
    extern __shared__ __align__(16) unsigned char smem[];
    uint4*  s_w   = (uint4*)smem;
    __half* s_h2  = (__half*)(smem + OFF_H2);
    float2* s_red = (float2*)(smem + OFF_RED);
    float*  s_c   = (float*)(smem + OFF_C);

    const int cta = blockIdx.x;
    const int b   = cta >> 3;
    const int k   = cta & 7;
    const int tid = threadIdx.x;
    const int wid = tid >> 5;
    const int lane = tid & 31;
    const int gid = lane >> 2;
    const int tig = lane & 3;

    unsigned* bar = &d_bar[b * 32];
    unsigned epoch = 0;
    const int blk  = k * 16 + wid;        // global 16-row block id within batch
    const int row0 = blk * 16;

    const uint4* Wg0 = d_w0f + ((size_t)b * 128 + blk) * (KT * 32);
    const uint4* Wg1 = d_w1f + ((size_t)b * 128 + blk) * (KT * 32);

    // ---- fill SMEM fragment cache: per warp, tiles 0..CKT-1 of each layer ----
    for (int i = tid; i < NWARP * WARP_CACHE_U4; i += TPB) {
        int w  = i / WARP_CACHE_U4;
        int r  = i % WARP_CACHE_U4;
        int l  = r / (CKT * 32);
        int rr = r % (CKT * 32);           // kt*32 + lane
        const uint4* src = (l ? d_w1f : d_w0f)
                         + ((size_t)b * 128 + k * 16 + w) * (KT * 32) + rr;
        s_w[i] = *src;
    }

    const float gw0 = __ldg(lnw + tid),       gb0 = __ldg(lnb + tid);
    const float gw1 = __ldg(lnw + DIM + tid), gb1 = __ldg(lnb + DIM + tid);

    float creg = 0.f;
    ((unsigned short*)s_h2)[tid] = 0;      // h = 0 (fp16)

    // initial prefetch for (t=0, l=0)
    uint4 pf[PF];
#pragma unroll
    for (int j = 0; j < PF; j++) pf[j] = __ldcg(&Wg0[(CKT + j) * 32 + lane]);

    __syncthreads();

    for (int t = 0; t < SEQ; t++) {
#pragma unroll
        for (int l = 0; l < 2; l++) {
            const float* add = (l == 0) ? (d_pre0 + ((size_t)b * SEQ + t) * G4)
                                        : (d_bias1 + (size_t)b * G4);
            float* gates = d_gates + (size_t)l * BATCH * G4 + (size_t)b * G4;
            const uint4* Wg = l ? Wg1 : Wg0;
            const uint4* Ws = s_w + wid * WARP_CACHE_U4 + l * (CKT * 32);
            const char* hbp = (const char*)s_h2 + tig * 8;

            float da[4] = {0.f, 0.f, 0.f, 0.f};
            float db[4] = {0.f, 0.f, 0.f, 0.f};
#pragma unroll
            for (int kt = 0; kt < KT; kt++) {
                uint4 v = (kt < CKT) ? Ws[kt * 32 + lane]
                        : (kt < CKT + PF) ? pf[kt - CKT]
                                          : __ldcg(&Wg[kt * 32 + lane]);
                uint2 hb = *(const uint2*)(hbp + kt * 32);
                if (kt & 1) { MMA16816(db, v, hb); }
                else        { MMA16816(da, v, hb); }
            }
            // every lane's D col is the gate (h replicated over columns)
            float g0 = da[0] + db[0] + __ldg(add + row0 + gid);
            float g1 = da[2] + db[2] + __ldg(add + row0 + 8 + gid);
            if (tig == 0) {
                gates[row0 + gid]     = g0;
                gates[row0 + 8 + gid] = g1;
            }

            // ---- prefetch next layer's streamed tiles NOW: latency hides behind
            //      reduction + barrier spin + stats load (weights are static) ----
#pragma unroll
            for (int j = 0; j < PF; j++)
                pf[j] = __ldcg(&((l ? Wg0 : Wg1)[(CKT + j) * 32 + lane]));

            float s1 = g0 + g1;
            float s2 = fmaf(g0, g0, g1 * g1);
#pragma unroll
            for (int o = 16; o >= 4; o >>= 1) {      // sums lanes 0,4,...,28
                s1 += __shfl_down_sync(0xffffffffu, s1, o);
                s2 += __shfl_down_sync(0xffffffffu, s2, o);
            }
            if (lane == 0) s_red[wid] = make_float2(s1, s2);
            __syncthreads();
            if (tid == 0) {
                float a = 0.f, c = 0.f;
#pragma unroll
                for (int i = 0; i < NWARP; i++) { a += s_red[i].x; c += s_red[i].y; }
                d_gstat[l * NCTA + cta] = make_float2(a, c);
            }
            group_barrier(bar, &epoch, tid);

            // ---- pointwise (redundant per CTA) ----
            {
                const int d = tid;
                const float gw = (l == 0) ? gw0 : gw1;
                const float gb = (l == 0) ? gb0 : gb1;
                const float4* st4 = (const float4*)(&d_gstat[l * NCTA + b * 8]);
                float m_[4], r_[4];
#pragma unroll
                for (int q = 0; q < 4; q++) {
                    float4 sv = __ldcg(st4 + q);
                    float s  = sv.x + sv.z;
                    float ss = sv.y + sv.w;
                    float m  = s * (1.f / 512.f);
                    float v  = fmaf(-m, m, ss * (1.f / 512.f));
                    m_[q] = m;
                    r_[q] = rsqrtf(v + LN_EPS);
                }
                float xi = __ldcg(gates + d);
                float xf = __ldcg(gates + 512 + d);
                float xg = __ldcg(gates + 1024 + d);
                float xo = __ldcg(gates + 1536 + d);
                float iv = sigmoidf_(fmaf((xi - m_[0]) * r_[0], gw, gb));
                float fv = sigmoidf_(fmaf((xf - m_[1]) * r_[1], gw, gb));
                float gv = tanhf_(   fmaf((xg - m_[2]) * r_[2], gw, gb));
                float ov = sigmoidf_(fmaf((xo - m_[3]) * r_[3], gw, gb));
                float cn = fmaf(fv, creg, iv * gv);
                creg = cn;

                float a = cn, c2 = cn * cn;
#pragma unroll
                for (int o = 16; o > 0; o >>= 1) {
                    a  += __shfl_down_sync(0xffffffffu, a, o);
                    c2 += __shfl_down_sync(0xffffffffu, c2, o);
                }
                if (lane == 0) s_red[wid] = make_float2(a, c2);
                __syncthreads();
                if (tid == 0) {
                    float sa = 0.f, sb = 0.f;
#pragma unroll
                    for (int i = 0; i < NWARP; i++) { sa += s_red[i].x; sb += s_red[i].y; }
                    float m = sa * (1.f / 512.f);
                    float v = fmaf(-m, m, sb * (1.f / 512.f));
                    s_c[0] = m;
                    s_c[1] = rsqrtf(v + LN_EPS);
                }
                __syncthreads();
                float cm = s_c[0], cr = s_c[1];
                float hv = ov * tanhf_(fmaf((cn - cm) * cr, gw, gb));
                s_h2[d] = __float2half_rn(hv);
                if (l == 1 && k == 0)
                    out[((size_t)b * SEQ + t) * DIM + d] = hv;
                __syncthreads();   // s_h2 ready before next matvec
            }
        }
    }
}

extern "C" void kernel_launch(void* const* d_in, const int* in_sizes, int n_in,
                              void* d_out, int out_size) {
    const float* x    = (const float*)d_in[0];
    const float* wih0 = (const float*)d_in[1];
    const float* whh0 = (const float*)d_in[2];
    const float* bih0 = (const float*)d_in[3];
    const float* bhh0 = (const float*)d_in[4];
    const float* wih1 = (const float*)d_in[5];
    const float* whh1 = (const float*)d_in[6];
    const float* bih1 = (const float*)d_in[7];
    const float* bhh1 = (const float*)d_in[8];
    const float* ln_w = (const float*)d_in[9];
    const float* ln_b = (const float*)d_in[10];
    float* out = (float*)d_out;

    cudaFuncSetAttribute(lstm_kernel, cudaFuncAttributeMaxDynamicSharedMemorySize,
                         SMEM_TOTAL);
    cudaFuncSetAttribute(gemm_pre0_h, cudaFuncAttributeMaxDynamicSharedMemorySize,
                         4 * KT * 32 * 16);

    prep_kernel<<<1024, 256>>>(x, wih0, whh0, wih1, whh1, bih1, bhh1);
    gemm_pre0_h<<<dim3(32, 16), 256, 4 * KT * 32 * 16>>>(bih0, bhh0);
    lstm_kernel<<<NCTA, TPB, SMEM_TOTAL>>>(ln_w, ln_b, out);
}

// round 16
// speedup vs baseline: 1.0304x; 1.0009x over previous
#include <cuda_runtime.h>
#include <cuda_fp16.h>
#include <cstdint>

#define BATCH 16
#define SEQ   256
#define DIM   512
#define G4    2048
#define LN_EPS 1e-5f

#define GROUPS 8                  // CTAs per batch
#define NCTA  (BATCH*GROUPS)     // 128
#define TPB   512
#define NWARP 16
#define KT    32                 // 16-wide k-tiles per row-block (512/16)
#define CKT   14                 // SMEM-cached k-tiles per layer per warp
#define RKT   4                  // register-pinned k-tiles per layer per warp
#define PF    6                  // register-prefetched streamed tiles
#define WARP_CACHE_U4 (2*CKT*32)               // 896 uint4/warp
#define SMEM_W_BYTES (NWARP*WARP_CACHE_U4*16)  // 229376
#define OFF_H2  SMEM_W_BYTES                   // fp16 h buffer (1 KB)
#define OFF_RED (OFF_H2 + 1024)
#define OFF_C   (OFF_RED + NWARP*8)
#define SMEM_TOTAL (OFF_C + 16)               // ~230.5 KB, 1 CTA/SM

#define NFRAG ((size_t)BATCH*128*KT*32)        // uint4 fragment chunks (32 MB each)
#define NXF   ((size_t)BATCH*32*KT*32)         // x B-fragments (uint2): 4 MB

// ---------------- static device scratch ----------------
__device__ uint4   d_w0f[NFRAG];              // whh0, A-fragment-major fp16
__device__ uint4   d_w1f[NFRAG];              // wih1+whh1, A-fragment-major fp16
__device__ uint4   d_wxf[NFRAG];              // wih0, A-fragment-major fp16
__device__ uint2   d_xf [NXF];                // x, B-fragment-major fp16
__device__ float   d_pre0[(size_t)BATCH*SEQ*G4];
__device__ float   d_bias1[BATCH*G4];
__device__ float   d_gates[2*BATCH*G4];       // double-buffered by layer
__device__ float2  d_gstat[2*NCTA];
__device__ unsigned d_bar[BATCH*32];

// ---------------- helpers ----------------
__device__ __forceinline__ unsigned f2h2(float a, float b) {
    __half2 h = __floats2half2_rn(a, b);
    return *reinterpret_cast<unsigned*>(&h);
}
__device__ __forceinline__ float sigmoidf_(float x) {
    return __fdividef(1.f, 1.f + __expf(-x));
}
__device__ __forceinline__ float tanhf_(float x) {
    x = fminf(fmaxf(x, -12.f), 12.f);
    float t = __expf(2.f * x);
    return __fdividef(t - 1.f, t + 1.f);
}

#define MMA16816(d, v, hb)                                                        \
    asm volatile("mma.sync.aligned.m16n8k16.row.col.f32.f16.f16.f32 "             \
                 "{%0,%1,%2,%3},{%4,%5,%6,%7},{%8,%9},{%0,%1,%2,%3};"             \
                 : "+f"(d[0]), "+f"(d[1]), "+f"(d[2]), "+f"(d[3])                 \
                 : "r"(v.x), "r"(v.z), "r"(v.y), "r"(v.w), "r"(hb.x), "r"(hb.y))

// ---------------- prep: build A/B-fragment fp16 tensors ----------------
__global__ void prep_kernel(const float* __restrict__ x,
                            const float* __restrict__ wih0,
                            const float* __restrict__ whh0,
                            const float* __restrict__ wih1,
                            const float* __restrict__ whh1,
                            const float* __restrict__ bih1,
                            const float* __restrict__ bhh1)
{
    size_t idx0 = (size_t)blockIdx.x * blockDim.x + threadIdx.x;
    size_t stride = (size_t)gridDim.x * blockDim.x;
    for (size_t i = idx0; i < NFRAG; i += stride) {
        unsigned lane = (unsigned)i & 31u;
        unsigned kt   = ((unsigned)(i >> 5)) & 31u;
        unsigned blk  = ((unsigned)(i >> 10)) & 127u;
        unsigned b    = (unsigned)(i >> 17);
        unsigned gid  = lane >> 2, tig = lane & 3;
        size_t s0 = ((size_t)b * G4 + blk * 16 + gid) * DIM + kt * 16 + tig * 4;
        size_t s1 = s0 + 8 * DIM;
        {
            float4 A0 = *(const float4*)(whh0 + s0);
            float4 A1 = *(const float4*)(whh0 + s1);
            uint4 o;
            o.x = f2h2(A0.x, A0.y); o.y = f2h2(A0.z, A0.w);
            o.z = f2h2(A1.x, A1.y); o.w = f2h2(A1.z, A1.w);
            d_w0f[i] = o;
        }
        {
            float4 A0 = *(const float4*)(wih0 + s0);
            float4 A1 = *(const float4*)(wih0 + s1);
            uint4 o;
            o.x = f2h2(A0.x, A0.y); o.y = f2h2(A0.z, A0.w);
            o.z = f2h2(A1.x, A1.y); o.w = f2h2(A1.z, A1.w);
            d_wxf[i] = o;
        }
        {
            float4 U0 = *(const float4*)(wih1 + s0);
            float4 V0 = *(const float4*)(whh1 + s0);
            float4 U1 = *(const float4*)(wih1 + s1);
            float4 V1 = *(const float4*)(whh1 + s1);
            uint4 o;
            o.x = f2h2(U0.x + V0.x, U0.y + V0.y); o.y = f2h2(U0.z + V0.z, U0.w + V0.w);
            o.z = f2h2(U1.x + V1.x, U1.y + V1.y); o.w = f2h2(U1.z + V1.z, U1.w + V1.w);
            d_w1f[i] = o;
        }
    }
    // x B-fragments: d_xf[((b*32+tg)*KT+kt)*32+lane] = x[b][tg*8+gid][kt*16+tig*4 ..+3]
    for (size_t i = idx0; i < NXF; i += stride) {
        unsigned lane = (unsigned)i & 31u;
        unsigned kt   = ((unsigned)(i >> 5)) & 31u;
        unsigned tg   = ((unsigned)(i >> 10)) & 31u;
        unsigned b    = (unsigned)(i >> 15);
        unsigned gid  = lane >> 2, tig = lane & 3;
        float4 xv = *(const float4*)(x + ((size_t)(b * SEQ + tg * 8 + gid) * DIM
                                          + kt * 16 + tig * 4));
        d_xf[i] = make_uint2(f2h2(xv.x, xv.y), f2h2(xv.z, xv.w));
    }
    if (idx0 < BATCH * G4) d_bias1[idx0] = bih1[idx0] + bhh1[idx0];
    if (idx0 < BATCH * 32) d_bar[idx0] = 0u;
}

// ---- HMMA GEMM: d_pre0[b][t][j] = wih0[b]@x[b,t] + bih0 + bhh0 ----
__global__ void __launch_bounds__(256) gemm_pre0_h(const float* __restrict__ bih0,
                                                   const float* __restrict__ bhh0)
{
    extern __shared__ __align__(16) unsigned char gsm[];
    uint4* s_a = (uint4*)gsm;                      // 4 * KT * 32 uint4 = 64 KB

    const int b  = blockIdx.y;
    const int rg = blockIdx.x;                     // 0..31 -> rowblocks rg*4..rg*4+3
    const int tid = threadIdx.x;
    const int wid = tid >> 5;
    const int lane = tid & 31;
    const int gid = lane >> 2;
    const int tig = lane & 3;

    const uint4* Asrc = d_wxf + ((size_t)b * 128 + rg * 4) * (KT * 32);
    for (int i = tid; i < 4 * KT * 32; i += 256) s_a[i] = Asrc[i];
    __syncthreads();

    const int rb = wid >> 1;
    const int row0g = (rg * 4 + rb) * 16;
    const uint4* As = s_a + rb * (KT * 32);
    const float bias0 = __ldg(bih0 + b * G4 + row0g + gid)
                      + __ldg(bhh0 + b * G4 + row0g + gid);
    const float bias1 = __ldg(bih0 + b * G4 + row0g + gid + 8)
                      + __ldg(bhh0 + b * G4 + row0g + gid + 8);

    const int tg0 = (wid & 1) * 16;
    for (int tg = tg0; tg < tg0 + 16; tg++) {
        const uint2* xf = d_xf + ((size_t)(b * 32 + tg) * KT) * 32;
        float d0[4] = {0.f, 0.f, 0.f, 0.f};
        float d1[4] = {0.f, 0.f, 0.f, 0.f};
#pragma unroll
        for (int kt = 0; kt < KT; kt++) {
            uint4 v  = As[kt * 32 + lane];
            uint2 hb = __ldg(&xf[kt * 32 + lane]);
            if (kt & 1) { MMA16816(d1, v, hb); }
            else        { MMA16816(d0, v, hb); }
        }
        const int t = tg * 8;
        float* base = d_pre0 + ((size_t)b * SEQ + t) * G4;
        base[(2 * tig)     * G4 + row0g + gid]     = d0[0] + d1[0] + bias0;
        base[(2 * tig + 1) * G4 + row0g + gid]     = d0[1] + d1[1] + bias0;
        base[(2 * tig)     * G4 + row0g + gid + 8] = d0[2] + d1[2] + bias1;
        base[(2 * tig + 1) * G4 + row0g + gid + 8] = d0[3] + d1[3] + bias1;
    }
}

// ---------------- persistent LSTM kernel ----------------
// Callers guarantee a __syncthreads already separates all threads' prior
// global stores from this call (sync -> elect -> release pattern), so the
// leading barrier is elided; only the post-spin sync remains.
__device__ __forceinline__ void group_barrier(unsigned* bar, unsigned* epoch, int tid) {
    *epoch += GROUPS;
    unsigned target = *epoch;
    if (tid == 0) {
        asm volatile("red.release.gpu.global.add.u32 [%0],%1;"
                     :: "l"(bar), "r"(1u) : "memory");
        unsigned v;
        do {
            asm volatile("ld.acquire.gpu.global.u32 %0,[%1];"
                         : "=r"(v) : "l"(bar) : "memory");
        } while (v < target);
    }
    __syncthreads();
}

__global__ void __launch_bounds__(TPB, 1)
lstm_kernel(const float* __restrict__ lnw, const float* __restrict__ lnb,
            float* __restrict__ out)
{
    extern __shared__ __align__(16) unsigned char smem[];
    uint4*  s_w   = (uint4*)smem;
    __half* s_h2  = (__half*)(smem + OFF_H2);
    float2* s_red = (float2*)(smem + OFF_RED);
    float*  s_c   = (float*)(smem + OFF_C);

    const int cta = blockIdx.x;
    const int b   = cta >> 3;
    const int k   = cta & 7;
    const int tid = threadIdx.x;
    const int wid = tid >> 5;
    const int lane = tid & 31;
    const int gid = lane >> 2;
    const int tig = lane & 3;

    unsigned* bar = &d_bar[b * 32];
    unsigned epoch = 0;
    const int blk  = k * 16 + wid;        // global 16-row block id within batch
    const int row0 = blk * 16;

    const uint4* Wg0 = d_w0f + ((size_t)b * 128 + blk) * (KT * 32);
    const uint4* Wg1 = d_w1f + ((size_t)b * 128 + blk) * (KT * 32);

    // ---- fill SMEM fragment cache: per warp, tiles 0..CKT-1 of each layer ----
    for (int i = tid; i < NWARP * WARP_CACHE_U4; i += TPB) {
        int w  = i / WARP_CACHE_U4;
        int r  = i % WARP_CACHE_U4;
        int l  = r / (CKT * 32);
        int rr = r % (CKT * 32);           // kt*32 + lane
        const uint4* src = (l ? d_w1f : d_w0f)
                         + ((size_t)b * 128 + k * 16 + w) * (KT * 32) + rr;
        s_w[i] = *src;
    }

    const float gw0 = __ldg(lnw + tid),       gb0 = __ldg(lnb + tid);
    const float gw1 = __ldg(lnw + DIM + tid), gb1 = __ldg(lnb + DIM + tid);

    float creg = 0.f;
    ((unsigned short*)s_h2)[tid] = 0;      // h = 0 (fp16)

    // ---- register-pinned weight tiles (persist all 256 steps) ----
    uint4 wr0[RKT], wr1[RKT];
#pragma unroll
    for (int j = 0; j < RKT; j++) {
        wr0[j] = __ldcg(&Wg0[(CKT + j) * 32 + lane]);
        wr1[j] = __ldcg(&Wg1[(CKT + j) * 32 + lane]);
    }

    // initial prefetch for (t=0, l=0): tiles CKT+RKT .. CKT+RKT+PF-1
    uint4 pf[PF];
#pragma unroll
    for (int j = 0; j < PF; j++) pf[j] = __ldcg(&Wg0[(CKT + RKT + j) * 32 + lane]);

    __syncthreads();

    for (int t = 0; t < SEQ; t++) {
#pragma unroll
        for (int l = 0; l < 2; l++) {
            const float* add = (l == 0) ? (d_pre0 + ((size_t)b * SEQ + t) * G4)
                                        : (d_bias1 + (size_t)b * G4);
            float* gates = d_gates + (size_t)l * BATCH * G4 + (size_t)b * G4;
            const uint4* Wg = l ? Wg1 : Wg0;
            const uint4* Ws = s_w + wid * WARP_CACHE_U4 + l * (CKT * 32);
            const char* hbp = (const char*)s_h2 + tig * 8;

            float da[4] = {0.f, 0.f, 0.f, 0.f};
            float db[4] = {0.f, 0.f, 0.f, 0.f};
#pragma unroll
            for (int kt = 0; kt < KT; kt++) {
                uint4 v = (kt < CKT) ? Ws[kt * 32 + lane]
                        : (kt < CKT + RKT) ? (l ? wr1[kt - CKT] : wr0[kt - CKT])
                        : (kt < CKT + RKT + PF) ? pf[kt - CKT - RKT]
                                                : __ldcg(&Wg[kt * 32 + lane]);
                uint2 hb = *(const uint2*)(hbp + kt * 32);
                if (kt & 1) { MMA16816(db, v, hb); }
                else        { MMA16816(da, v, hb); }
            }
            // every lane's D col is the gate (h replicated over columns)
            float g0 = da[0] + db[0] + __ldg(add + row0 + gid);
            float g1 = da[2] + db[2] + __ldg(add + row0 + 8 + gid);
            if (tig == 0) {
                gates[row0 + gid]     = g0;
                gates[row0 + 8 + gid] = g1;
            }

            // ---- prefetch next layer's streamed tiles NOW: latency hides behind
            //      reduction + barrier spin + stats load (weights are static) ----
#pragma unroll
            for (int j = 0; j < PF; j++)
                pf[j] = __ldcg(&((l ? Wg0 : Wg1)[(CKT + RKT + j) * 32 + lane]));

            float s1 = g0 + g1;
            float s2 = fmaf(g0, g0, g1 * g1);
#pragma unroll
            for (int o = 16; o >= 4; o >>= 1) {      // sums lanes 0,4,...,28
                s1 += __shfl_down_sync(0xffffffffu, s1, o);
                s2 += __shfl_down_sync(0xffffffffu, s2, o);
            }
            if (lane == 0) s_red[wid] = make_float2(s1, s2);
            __syncthreads();
            if (tid == 0) {
                float a = 0.f, c = 0.f;
#pragma unroll
                for (int i = 0; i < NWARP; i++) { a += s_red[i].x; c += s_red[i].y; }
                d_gstat[l * NCTA + cta] = make_float2(a, c);
            }
            group_barrier(bar, &epoch, tid);

            // ---- pointwise (redundant per CTA) ----
            {
                const int d = tid;
                const float gw = (l == 0) ? gw0 : gw1;
                const float gb = (l == 0) ? gb0 : gb1;
                const float4* st4 = (const float4*)(&d_gstat[l * NCTA + b * 8]);
                float m_[4], r_[4];
#pragma unroll
                for (int q = 0; q < 4; q++) {
                    float4 sv = __ldcg(st4 + q);
                    float s  = sv.x + sv.z;
                    float ss = sv.y + sv.w;
                    float m  = s * (1.f / 512.f);
                    float v  = fmaf(-m, m, ss * (1.f / 512.f));
                    m_[q] = m;
                    r_[q] = rsqrtf(v + LN_EPS);
                }
                float xi = __ldcg(gates + d);
                float xf = __ldcg(gates + 512 + d);
                float xg = __ldcg(gates + 1024 + d);
                float xo = __ldcg(gates + 1536 + d);
                float iv = sigmoidf_(fmaf((xi - m_[0]) * r_[0], gw, gb));
                float fv = sigmoidf_(fmaf((xf - m_[1]) * r_[1], gw, gb));
                float gv = tanhf_(   fmaf((xg - m_[2]) * r_[2], gw, gb));
                float ov = sigmoidf_(fmaf((xo - m_[3]) * r_[3], gw, gb));
                float cn = fmaf(fv, creg, iv * gv);
                creg = cn;

                float a = cn, c2 = cn * cn;
#pragma unroll
                for (int o = 16; o > 0; o >>= 1) {
                    a  += __shfl_down_sync(0xffffffffu, a, o);
                    c2 += __shfl_down_sync(0xffffffffu, c2, o);
                }
                if (lane == 0) s_red[wid] = make_float2(a, c2);
                __syncthreads();
                if (tid == 0) {
                    float sa = 0.f, sb = 0.f;
#pragma unroll
                    for (int i = 0; i < NWARP; i++) { sa += s_red[i].x; sb += s_red[i].y; }
                    float m = sa * (1.f / 512.f);
                    float v = fmaf(-m, m, sb * (1.f / 512.f));
                    s_c[0] = m;
                    s_c[1] = rsqrtf(v + LN_EPS);
                }
                __syncthreads();
                float cm = s_c[0], cr = s_c[1];
                float hv = ov * tanhf_(fmaf((cn - cm) * cr, gw, gb));
                s_h2[d] = __float2half_rn(hv);
                if (l == 1 && k == 0)
                    out[((size_t)b * SEQ + t) * DIM + d] = hv;
                __syncthreads();   // s_h2 ready before next matvec
            }
        }
    }
}

extern "C" void kernel_launch(void* const* d_in, const int* in_sizes, int n_in,
                              void* d_out, int out_size) {
    const float* x    = (const float*)d_in[0];
    const float* wih0 = (const float*)d_in[1];
    const float* whh0 = (const float*)d_in[2];
    const float* bih0 = (const float*)d_in[3];
    const float* bhh0 = (const float*)d_in[4];
    const float* wih1 = (const float*)d_in[5];
    const float* whh1 = (const float*)d_in[6];
    const float* bih1 = (const float*)d_in[7];
    const float* bhh1 = (const float*)d_in[8];
    const float* ln_w = (const float*)d_in[9];
    const float* ln_b = (const float*)d_in[10];
    float* out = (float*)d_out;

    cudaFuncSetAttribute(lstm_kernel, cudaFuncAttributeMaxDynamicSharedMemorySize,
                         SMEM_TOTAL);
    cudaFuncSetAttribute(gemm_pre0_h, cudaFuncAttributeMaxDynamicSharedMemorySize,
                         4 * KT * 32 * 16);

    prep_kernel<<<1024, 256>>>(x, wih0, whh0, wih1, whh1, bih1, bhh1);
    gemm_pre0_h<<<dim3(32, 16), 256, 4 * KT * 32 * 16>>>(bih0, bhh0);
    lstm_kernel<<<NCTA, TPB, SMEM_TOTAL>>>(ln_w, ln_b, out);
}